// round 16
// baseline (speedup 1.0000x reference)
#include <cuda_runtime.h>
#include <cuda_fp16.h>
#include <cstdint>

// ---------------- problem-size constants (fixed by this problem) -------------
#define MAXN   100000
#define NREL   8
#define INF    128
#define HID    32
#define NCOLS  (NREL*HID)      // 256
#define NGMAX  64
#define EPB    1024            // edges per block in scatter2

// ---------------- device scratch (static: no allocations allowed) ------------
// Replay-safety: h1 zeroed by k_prep at the START of every replay; deg arrays
// self-reset in k_prep; g_cnt resets in k_scatter1 block 0.
__device__ __align__(128) __half g_y1h[(size_t)MAXN * NCOLS]; // fp16 y1 * rso (51MB)
__device__ __align__(128) float g_h1[(size_t)MAXN * HID];     // scatter1 accum
__device__ __align__(128) float g_dot[(size_t)MAXN * 16];     // relu(h1+b)·V_r, [n][r][2]
__device__ __align__(128) float g_rso[NREL * MAXN];           // rsqrt(max(deg_out,1))
__device__ __align__(128) float g_rsi[NREL * MAXN];           // rsqrt(max(deg_in,1))
__device__ __align__(128) int   g_dego[NREL * MAXN];          // reset by k_prep
__device__ __align__(128) int   g_degi[NREL * MAXN];          // reset by k_prep
__device__ __align__(128) int   g_cnt[NGMAX];                 // reset by k_scatter1
__device__ __align__(128) float g_inv[NGMAX];                 // 1/max(cnt,1)
__device__ __align__(128) float g_V[NREL * HID * 2];          // W2_r @ Wc
// fp16 weight image, [n][k] layout, 256B/row
__device__ __align__(128) unsigned char g_wimg[65536];

__device__ __forceinline__ uint32_t smem_u32(const void* p) {
    uint32_t a;
    asm("{ .reg .u64 t; cvta.to.shared.u64 t, %1; cvt.u32.u64 %0, t; }" : "=r"(a) : "l"(p));
    return a;
}
__device__ __forceinline__ void cp16(uint32_t daddr, const void* src) {
    asm volatile("cp.async.cg.shared.global [%0], [%1], 16;" :: "r"(daddr), "l"(src));
}
__device__ __forceinline__ void ldsm4(uint32_t* r, uint32_t addr) {
    asm volatile("ldmatrix.sync.aligned.m8n8.x4.shared.b16 {%0,%1,%2,%3}, [%4];"
        : "=r"(r[0]), "=r"(r[1]), "=r"(r[2]), "=r"(r[3]) : "r"(addr));
}
// div by n_edges: fixed-shape fast path compiles to mul-shift (no runtime div)
__device__ __forceinline__ int divE(int e, int n_edges) {
    return (n_edges == 80000) ? (e / 80000) : (e / n_edges);
}

// ---------------- K2: wconv (blocks 0-63) + degrees + graph counts ------------
__global__ void k_deg(const int* __restrict__ src, const int* __restrict__ dst,
                      const int* __restrict__ gids, const float* __restrict__ W1,
                      int n_nodes, int n_edges) {
    if (blockIdx.x < 64) {
        int i = blockIdx.x * blockDim.x + threadIdx.x;   // 0..16383
        int n = i >> 6, k = (i & 63) * 2;
        int r = n >> 5, f = n & 31;
        float w0 = W1[r * (INF * HID) + k * HID + f];
        float w1 = W1[r * (INF * HID) + (k + 1) * HID + f];
        __half2 hv;
        hv.x = __float2half(w0);
        hv.y = __float2half(w1);
        *(__half2*)(g_wimg + (uint32_t)n * 256u + (uint32_t)k * 2u) = hv;
        return;
    }
    int i = (blockIdx.x - 64) * blockDim.x + threadIdx.x;
    int te = NREL * n_edges;
    if (i < te) {
        int r = divE(i, n_edges);
        atomicAdd(&g_dego[r * n_nodes + src[i]], 1);
        atomicAdd(&g_degi[r * n_nodes + dst[i]], 1);
    } else if (i < te + n_nodes) {
        atomicAdd(&g_cnt[gids[i - te]], 1);
    }
}

// ------ K3: rsqrt tables, V, out init, deg reset, h1 zero (replay start) -----
__global__ void k_prep(const float* __restrict__ W2, const float* __restrict__ Wc,
                       const float* __restrict__ b2, const float* __restrict__ bc,
                       float* __restrict__ out, int n_nodes, int n_graphs) {
    int i = blockIdx.x * blockDim.x + threadIdx.x;
    int t1 = NREL * n_nodes;
    int t2 = t1 + NREL * HID * 2;
    int t3 = t2 + 2 * n_graphs;
    if (i < t1) {
        g_rso[i] = rsqrtf((float)max(g_dego[i], 1));
        g_rsi[i] = rsqrtf((float)max(g_degi[i], 1));
        g_dego[i] = 0;                 // self-reset for next graph replay
        g_degi[i] = 0;
    } else if (i < t2) {
        int v = i - t1;
        int r = v >> 6, f = (v >> 1) & 31, o = v & 1;
        float s = 0.f;
        #pragma unroll
        for (int j = 0; j < HID; j++) s += W2[r * (HID * HID) + f * HID + j] * Wc[j * 2 + o];
        g_V[v] = s;
    } else if (i < t3) {
        int u = i - t2;
        int g = u >> 1, o = u & 1;
        if (o == 0) g_inv[g] = 1.f / (float)max(g_cnt[g], 1);
        float s = 0.f;
        for (int j = 0; j < HID; j++) {
            float bs = 0.f;
            #pragma unroll
            for (int r = 0; r < NREL; r++) bs += b2[r * HID + j];
            s += bs * Wc[j * 2 + o];
        }
        out[u] = bc[o] + (g_cnt[g] > 0 ? s : 0.f);   // empty graph -> pooled = 0
    } else if (i < t3 + (n_nodes * HID) / 4) {
        ((float4*)g_h1)[i - t3] = make_float4(0.f, 0.f, 0.f, 0.f);
    }
}

// ---------------- K4: HMMA GEMM  y1h = (x @ W1) * rso, fp16 -------------------
// CTA: 64 nodes x ALL 256 cols x full K=128 (x read once). Single-pass fp16.
// smem 87KB -> 2 CTAs/SM. 8 warps (2M x 4N), warp tile 32x64, acc 64 regs.
#define SROW  272
#define SA_H  0
#define SB_H  (64 * SROW)                // 17408
#define SMEM_G (SB_H + 256 * SROW)       // 87040

__device__ __forceinline__ void mma16816(float* c, const uint32_t* a, const uint32_t* b) {
    asm volatile("mma.sync.aligned.m16n8k16.row.col.f32.f16.f16.f32 "
        "{%0,%1,%2,%3}, {%4,%5,%6,%7}, {%8,%9}, {%0,%1,%2,%3};"
        : "+f"(c[0]), "+f"(c[1]), "+f"(c[2]), "+f"(c[3])
        : "r"(a[0]), "r"(a[1]), "r"(a[2]), "r"(a[3]), "r"(b[0]), "r"(b[1]));
}

__global__ __launch_bounds__(256, 2) void k_gemm_mma(const float* __restrict__ x,
                                                     int n_nodes) {
    extern __shared__ unsigned char smem[];
    uint32_t sb = smem_u32(smem);
    int t = threadIdx.x, wid = t >> 5, lid = t & 31;
    int gid = lid >> 2, tid4 = lid & 3;
    int node0 = blockIdx.x * 64;

    // ---- B: cp.async of the FULL fp16 weight image (256 rows) ----------------
    {
        const unsigned char* bh = g_wimg;
        #pragma unroll
        for (int p = 0; p < 16; p++) {
            int idx = p * 256 + t;               // 0..4095
            int n = idx >> 4, c = idx & 15;      // n 0..255, c 0..15
            uint32_t so = (uint32_t)n * 256u + (uint32_t)c * 16u;
            cp16(sb + SB_H + n * SROW + c * 16, bh + so);
        }
        asm volatile("cp.async.commit_group;" ::: "memory");
    }
    // ---- A: load x, convert to fp16, store (overlaps B cp.async) -------------
    #pragma unroll
    for (int p = 0; p < 8; p++) {
        int idx = p * 256 + t;                   // 0..2047
        int m = idx >> 5, k = (idx & 31) * 4;    // m 0..63
        int gn = node0 + m;
        float4 v = make_float4(0.f, 0.f, 0.f, 0.f);
        if (gn < n_nodes) v = *(const float4*)(x + (size_t)gn * INF + k);
        __half2 a, b;
        a.x = __float2half(v.x); a.y = __float2half(v.y);
        b.x = __float2half(v.z); b.y = __float2half(v.w);
        uint2 hp; hp.x = *(uint32_t*)&a; hp.y = *(uint32_t*)&b;
        *(uint2*)(smem + SA_H + m * SROW + k * 2) = hp;
    }
    asm volatile("cp.async.wait_group 0;" ::: "memory");
    __syncthreads();

    int mrow0 = (wid >> 2) * 32;         // 2 M-groups
    int ncol0 = (wid & 3) * 64;          // 4 N-groups of 64 cols (2 relations)
    float acc[2][8][4];
    #pragma unroll
    for (int mi = 0; mi < 2; mi++)
        #pragma unroll
        for (int ni = 0; ni < 8; ni++)
            #pragma unroll
            for (int q = 0; q < 4; q++) acc[mi][ni][q] = 0.f;

    int l3 = lid & 7, grp = lid >> 3;
    uint32_t a_row = mrow0 + l3 + (grp & 1) * 8;
    uint32_t a_koff = (grp >> 1) * 16;
    uint32_t aH0 = sb + SA_H + a_row * SROW + a_koff;
    uint32_t aH1 = aH0 + 16 * SROW;
    uint32_t b_row = ncol0 + l3 + (grp >> 1) * 8;
    uint32_t b_koff = (grp & 1) * 16;
    uint32_t bH = sb + SB_H + b_row * SROW + b_koff;

    #pragma unroll
    for (int ks = 0; ks < 8; ks++) {
        uint32_t kb = ks * 32;
        uint32_t ah[2][4];
        ldsm4(ah[0], aH0 + kb);
        ldsm4(ah[1], aH1 + kb);
        #pragma unroll
        for (int p = 0; p < 4; p++) {        // ni pair (2p, 2p+1)
            uint32_t bh4[4];
            ldsm4(bh4, bH + p * 16 * SROW + kb);
            #pragma unroll
            for (int h = 0; h < 2; h++) {
                int ni = 2 * p + h;
                mma16816(acc[0][ni], ah[0], &bh4[2 * h]);
                mma16816(acc[1][ni], ah[1], &bh4[2 * h]);
            }
        }
    }

    // ---- epilogue: scale by rso (2 relations per warp) and store fp16 --------
    int relbase = ncol0 >> 5;            // relations relbase, relbase+1
    #pragma unroll
    for (int mi = 0; mi < 2; mi++) {
        int r0 = node0 + mrow0 + mi * 16 + gid;
        float sc0[2] = {0.f, 0.f}, sc1[2] = {0.f, 0.f};
        if (r0 < n_nodes) {
            sc0[0] = g_rso[relbase * n_nodes + r0];
            sc0[1] = g_rso[(relbase + 1) * n_nodes + r0];
        }
        if (r0 + 8 < n_nodes) {
            sc1[0] = g_rso[relbase * n_nodes + r0 + 8];
            sc1[1] = g_rso[(relbase + 1) * n_nodes + r0 + 8];
        }
        #pragma unroll
        for (int ni = 0; ni < 8; ni++) {
            int col = ncol0 + ni * 8 + tid4 * 2;
            int rh = ni >> 2;
            if (r0 < n_nodes) {
                __half2 v; v.x = __float2half(acc[mi][ni][0] * sc0[rh]);
                           v.y = __float2half(acc[mi][ni][1] * sc0[rh]);
                *(__half2*)(g_y1h + (size_t)r0 * NCOLS + col) = v;
            }
            if (r0 + 8 < n_nodes) {
                __half2 v; v.x = __float2half(acc[mi][ni][2] * sc1[rh]);
                           v.y = __float2half(acc[mi][ni][3] * sc1[rh]);
                *(__half2*)(g_y1h + (size_t)(r0 + 8) * NCOLS + col) = v;
            }
        }
    }
}

// ------- K5: layer-1 edge scatter, ONE THREAD PER EDGE; resets g_cnt ----------
// Per edge: 2 idx LDG + 1 rsi LDG + 4x LDG.128 (64B y row) + 8x RED.128,
// vs 32 LDG + 8 RED with the old 8-threads/edge layout (LDG dispatch floor
// was the binding resource: issue=40%, no memory % saturated).
__global__ void k_scatter1(const int* __restrict__ src, const int* __restrict__ dst,
                           int n_nodes, int n_edges) {
    if (blockIdx.x == 0 && threadIdx.x < NGMAX) g_cnt[threadIdx.x] = 0;
    int e = blockIdx.x * blockDim.x + threadIdx.x;
    if (e >= NREL * n_edges) return;
    int r = divE(e, n_edges);
    int s = src[e], d = dst[e];
    float sc = g_rsi[r * n_nodes + d];
    const uint4* yp = (const uint4*)(g_y1h + (size_t)s * NCOLS + r * HID);
    uint4 w0 = yp[0], w1 = yp[1], w2 = yp[2], w3 = yp[3];   // 4-way MLP gather
    float4* hp = (float4*)(g_h1 + (size_t)d * HID);
    uint4 wv[4] = {w0, w1, w2, w3};
    #pragma unroll
    for (int j = 0; j < 4; j++) {
        float2 fa = __half22float2(*(__half2*)&wv[j].x);
        float2 fb = __half22float2(*(__half2*)&wv[j].y);
        float2 fc = __half22float2(*(__half2*)&wv[j].z);
        float2 fd = __half22float2(*(__half2*)&wv[j].w);
        atomicAdd(&hp[2 * j],     make_float4(fa.x * sc, fa.y * sc, fb.x * sc, fb.y * sc));
        atomicAdd(&hp[2 * j + 1], make_float4(fc.x * sc, fc.y * sc, fd.x * sc, fd.y * sc));
    }
}

// ---- K6: per-node dot precompute: dot[n][r][:] = relu(h1[n]+bias) . V_r ------
__global__ __launch_bounds__(256) void k_dot(const float* __restrict__ b1,
                                             int n_nodes) {
    __shared__ float hs[32][33];
    __shared__ float Vs[NREL * HID * 2];
    __shared__ float bias[HID];
    int t = threadIdx.x;
    for (int i = t; i < NREL * HID * 2; i += 256) Vs[i] = g_V[i];
    if (t < HID) {
        float s = 0.f;
        #pragma unroll
        for (int r = 0; r < NREL; r++) s += b1[r * HID + t];
        bias[t] = s;
    }
    __syncthreads();
    int node0 = blockIdx.x * 32;
    {
        int n = t >> 3, q = t & 7;
        int gn = node0 + n;
        float4 v = make_float4(0.f, 0.f, 0.f, 0.f);
        if (gn < n_nodes) v = ((const float4*)(g_h1 + (size_t)gn * HID))[q];
        hs[n][q * 4 + 0] = fmaxf(v.x + bias[q * 4 + 0], 0.f);
        hs[n][q * 4 + 1] = fmaxf(v.y + bias[q * 4 + 1], 0.f);
        hs[n][q * 4 + 2] = fmaxf(v.z + bias[q * 4 + 2], 0.f);
        hs[n][q * 4 + 3] = fmaxf(v.w + bias[q * 4 + 3], 0.f);
    }
    __syncthreads();
    int n2 = t & 31, r2 = t >> 5;
    const float* vp = Vs + r2 * (HID * 2);
    float a0 = 0.f, a1 = 0.f;
    #pragma unroll
    for (int j = 0; j < HID; j++) {
        float h = hs[n2][j];
        a0 += h * vp[2 * j + 0];
        a1 += h * vp[2 * j + 1];
    }
    int gn2 = node0 + n2;
    if (gn2 < n_nodes)
        *(float2*)(g_dot + (size_t)gn2 * 16 + r2 * 2) = make_float2(a0, a1);
}

// ---- K7: layer-2 edge pass + mean-pool + classifier (8B gather per edge) ----
__global__ __launch_bounds__(256) void k_scatter2(const int* __restrict__ src,
                                                  const int* __restrict__ dst,
                                                  const int* __restrict__ gids,
                                                  float* __restrict__ out,
                                                  int n_nodes, int n_edges) {
    __shared__ float zs[NGMAX * 2];
    __shared__ float inv_s[NGMAX];
    int t = threadIdx.x;
    if (t < NGMAX * 2) zs[t] = 0.f;
    if (t < NGMAX) inv_s[t] = g_inv[t];
    __syncthreads();

    int te = NREL * n_edges;
    int e0 = blockIdx.x * EPB;
    #pragma unroll
    for (int it = 0; it < EPB / 256; it++) {
        int e = e0 + it * 256 + t;
        if (e < te) {
            int r = divE(e, n_edges);
            int s = src[e], d = dst[e];
            int g = gids[d];
            float coeff = g_rso[r * n_nodes + s] * g_rsi[r * n_nodes + d] * inv_s[g];
            float2 dv = *(const float2*)(g_dot + (size_t)s * 16 + r * 2);
            atomicAdd(&zs[g * 2 + 0], dv.x * coeff);
            atomicAdd(&zs[g * 2 + 1], dv.y * coeff);
        }
    }
    __syncthreads();
    if (t < NGMAX * 2) atomicAdd(&out[t], zs[t]);
}

// ---------------- launch ------------------------------------------------------
extern "C" void kernel_launch(void* const* d_in, const int* in_sizes, int n_in,
                              void* d_out, int out_size) {
    int off = (n_in >= 11) ? 1 : 0;
    const float* x   = (const float*)d_in[0];
    const int*   src = (const int*)d_in[1];
    const int*   dst = (const int*)d_in[2];
    const int*   gid = (const int*)d_in[3];
    const float* W1  = (const float*)d_in[4 + off];
    const float* b1  = (const float*)d_in[5 + off];
    const float* W2  = (const float*)d_in[6 + off];
    const float* b2  = (const float*)d_in[7 + off];
    const float* Wc  = (const float*)d_in[8 + off];
    const float* bc  = (const float*)d_in[9 + off];
    float* out = (float*)d_out;

    int n_nodes  = in_sizes[3];
    int n_edges  = in_sizes[1] / NREL;
    int n_graphs = out_size / 2;

    cudaFuncSetAttribute(k_gemm_mma, cudaFuncAttributeMaxDynamicSharedMemorySize,
                         SMEM_G);

    int tot1 = NREL * n_edges + n_nodes;
    k_deg<<<64 + (tot1 + 255) / 256, 256>>>(src, dst, gid, W1, n_nodes, n_edges);

    int tot2 = NREL * n_nodes + NREL * HID * 2 + 2 * n_graphs + (n_nodes * HID) / 4;
    k_prep<<<(tot2 + 255) / 256, 256>>>(W2, Wc, b2, bc, out, n_nodes, n_graphs);

    k_gemm_mma<<<(n_nodes + 63) / 64, 256, SMEM_G>>>(x, n_nodes);

    int tot5 = NREL * n_edges;
    k_scatter1<<<(tot5 + 255) / 256, 256>>>(src, dst, n_nodes, n_edges);

    k_dot<<<(n_nodes + 31) / 32, 256>>>(b1, n_nodes);

    k_scatter2<<<(NREL * n_edges + EPB - 1) / EPB, 256>>>(src, dst, gid, out,
                                                          n_nodes, n_edges);
}

// round 17
// speedup vs baseline: 1.0385x; 1.0385x over previous
#include <cuda_runtime.h>
#include <cuda_fp16.h>
#include <cstdint>

// ---------------- problem-size constants (fixed by this problem) -------------
#define MAXN   100000
#define NREL   8
#define INF    128
#define HID    32
#define NCOLS  (NREL*HID)      // 256
#define NGMAX  64
#define EPB    1024            // edges per block in scatter2

// ---------------- device scratch (static: no allocations allowed) ------------
// Replay-safety: h1 zeroed by k_prep at the START of every replay; deg arrays
// self-reset in k_prep; g_cnt resets in k_scatter1 block 0.
__device__ __align__(128) __half g_y1h[(size_t)MAXN * NCOLS]; // fp16 x@W1 (51MB)
__device__ __align__(128) float g_h1[(size_t)MAXN * HID];     // scatter1 accum
__device__ __align__(128) float g_dot[(size_t)MAXN * 16];     // relu(h1+b)·V_r, [n][r][2]
__device__ __align__(128) float g_rso[NREL * MAXN];           // rsqrt(max(deg_out,1))
__device__ __align__(128) float g_rsi[NREL * MAXN];           // rsqrt(max(deg_in,1))
__device__ __align__(128) int   g_dego[NREL * MAXN];          // reset by k_prep
__device__ __align__(128) int   g_degi[NREL * MAXN];          // reset by k_prep
__device__ __align__(128) int   g_cnt[NGMAX];                 // reset by k_scatter1
__device__ __align__(128) float g_inv[NGMAX];                 // 1/max(cnt,1)
__device__ __align__(128) float g_V[NREL * HID * 2];          // W2_r @ Wc
// fp16 weight image, [n][k] layout, 256B/row
__device__ __align__(128) unsigned char g_wimg[65536];

__device__ __forceinline__ uint32_t smem_u32(const void* p) {
    uint32_t a;
    asm("{ .reg .u64 t; cvta.to.shared.u64 t, %1; cvt.u32.u64 %0, t; }" : "=r"(a) : "l"(p));
    return a;
}
__device__ __forceinline__ void cp16(uint32_t daddr, const void* src) {
    asm volatile("cp.async.cg.shared.global [%0], [%1], 16;" :: "r"(daddr), "l"(src));
}
__device__ __forceinline__ void ldsm4(uint32_t* r, uint32_t addr) {
    asm volatile("ldmatrix.sync.aligned.m8n8.x4.shared.b16 {%0,%1,%2,%3}, [%4];"
        : "=r"(r[0]), "=r"(r[1]), "=r"(r[2]), "=r"(r[3]) : "r"(addr));
}
// div by n_edges: fixed-shape fast path compiles to mul-shift (no runtime div)
__device__ __forceinline__ int divE(int e, int n_edges) {
    return (n_edges == 80000) ? (e / 80000) : (e / n_edges);
}

// ---------------- K1: W1 -> fp16 image (stream A, feeds GEMM) -----------------
__global__ void k_wconv(const float* __restrict__ W1) {
    int i = blockIdx.x * blockDim.x + threadIdx.x;   // 0..16383
    int n = i >> 6, k = (i & 63) * 2;
    int r = n >> 5, f = n & 31;
    float w0 = W1[r * (INF * HID) + k * HID + f];
    float w1 = W1[r * (INF * HID) + (k + 1) * HID + f];
    __half2 hv;
    hv.x = __float2half(w0);
    hv.y = __float2half(w1);
    *(__half2*)(g_wimg + (uint32_t)n * 256u + (uint32_t)k * 2u) = hv;
}

// ---------------- K2: degrees + graph counts (stream B) -----------------------
__global__ void k_deg(const int* __restrict__ src, const int* __restrict__ dst,
                      const int* __restrict__ gids, int n_nodes, int n_edges) {
    int i = blockIdx.x * blockDim.x + threadIdx.x;
    int te = NREL * n_edges;
    if (i < te) {
        int r = divE(i, n_edges);
        atomicAdd(&g_dego[r * n_nodes + src[i]], 1);
        atomicAdd(&g_degi[r * n_nodes + dst[i]], 1);
    } else if (i < te + n_nodes) {
        atomicAdd(&g_cnt[gids[i - te]], 1);
    }
}

// ------ K3: rsqrt tables, V, out init, deg reset, h1 zero (stream B) ---------
__global__ void k_prep(const float* __restrict__ W2, const float* __restrict__ Wc,
                       const float* __restrict__ b2, const float* __restrict__ bc,
                       float* __restrict__ out, int n_nodes, int n_graphs) {
    int i = blockIdx.x * blockDim.x + threadIdx.x;
    int t1 = NREL * n_nodes;
    int t2 = t1 + NREL * HID * 2;
    int t3 = t2 + 2 * n_graphs;
    if (i < t1) {
        g_rso[i] = rsqrtf((float)max(g_dego[i], 1));
        g_rsi[i] = rsqrtf((float)max(g_degi[i], 1));
        g_dego[i] = 0;                 // self-reset for next graph replay
        g_degi[i] = 0;
    } else if (i < t2) {
        int v = i - t1;
        int r = v >> 6, f = (v >> 1) & 31, o = v & 1;
        float s = 0.f;
        #pragma unroll
        for (int j = 0; j < HID; j++) s += W2[r * (HID * HID) + f * HID + j] * Wc[j * 2 + o];
        g_V[v] = s;
    } else if (i < t3) {
        int u = i - t2;
        int g = u >> 1, o = u & 1;
        if (o == 0) g_inv[g] = 1.f / (float)max(g_cnt[g], 1);
        float s = 0.f;
        for (int j = 0; j < HID; j++) {
            float bs = 0.f;
            #pragma unroll
            for (int r = 0; r < NREL; r++) bs += b2[r * HID + j];
            s += bs * Wc[j * 2 + o];
        }
        out[u] = bc[o] + (g_cnt[g] > 0 ? s : 0.f);   // empty graph -> pooled = 0
    } else if (i < t3 + (n_nodes * HID) / 4) {
        ((float4*)g_h1)[i - t3] = make_float4(0.f, 0.f, 0.f, 0.f);
    }
}

// ---------------- K4: HMMA GEMM  y1h = x @ W1 (fp16, NO rso fold) -------------
// CTA: 64 nodes x ALL 256 cols x full K=128 (x read once). Single-pass fp16.
// rso fold moved back to scatter1 so the GEMM depends only on x + wimg and can
// overlap deg/prep on a second capture-graph branch.
#define SROW  272
#define SA_H  0
#define SB_H  (64 * SROW)                // 17408
#define SMEM_G (SB_H + 256 * SROW)       // 87040

__device__ __forceinline__ void mma16816(float* c, const uint32_t* a, const uint32_t* b) {
    asm volatile("mma.sync.aligned.m16n8k16.row.col.f32.f16.f16.f32 "
        "{%0,%1,%2,%3}, {%4,%5,%6,%7}, {%8,%9}, {%0,%1,%2,%3};"
        : "+f"(c[0]), "+f"(c[1]), "+f"(c[2]), "+f"(c[3])
        : "r"(a[0]), "r"(a[1]), "r"(a[2]), "r"(a[3]), "r"(b[0]), "r"(b[1]));
}

__global__ __launch_bounds__(256, 2) void k_gemm_mma(const float* __restrict__ x,
                                                     int n_nodes) {
    extern __shared__ unsigned char smem[];
    uint32_t sb = smem_u32(smem);
    int t = threadIdx.x, wid = t >> 5, lid = t & 31;
    int gid = lid >> 2, tid4 = lid & 3;
    int node0 = blockIdx.x * 64;

    // ---- B: cp.async of the FULL fp16 weight image (256 rows) ----------------
    {
        const unsigned char* bh = g_wimg;
        #pragma unroll
        for (int p = 0; p < 16; p++) {
            int idx = p * 256 + t;               // 0..4095
            int n = idx >> 4, c = idx & 15;      // n 0..255, c 0..15
            uint32_t so = (uint32_t)n * 256u + (uint32_t)c * 16u;
            cp16(sb + SB_H + n * SROW + c * 16, bh + so);
        }
        asm volatile("cp.async.commit_group;" ::: "memory");
    }
    // ---- A: load x, convert to fp16, store (overlaps B cp.async) -------------
    #pragma unroll
    for (int p = 0; p < 8; p++) {
        int idx = p * 256 + t;                   // 0..2047
        int m = idx >> 5, k = (idx & 31) * 4;    // m 0..63
        int gn = node0 + m;
        float4 v = make_float4(0.f, 0.f, 0.f, 0.f);
        if (gn < n_nodes) v = *(const float4*)(x + (size_t)gn * INF + k);
        __half2 a, b;
        a.x = __float2half(v.x); a.y = __float2half(v.y);
        b.x = __float2half(v.z); b.y = __float2half(v.w);
        uint2 hp; hp.x = *(uint32_t*)&a; hp.y = *(uint32_t*)&b;
        *(uint2*)(smem + SA_H + m * SROW + k * 2) = hp;
    }
    asm volatile("cp.async.wait_group 0;" ::: "memory");
    __syncthreads();

    int mrow0 = (wid >> 2) * 32;         // 2 M-groups
    int ncol0 = (wid & 3) * 64;          // 4 N-groups of 64 cols
    float acc[2][8][4];
    #pragma unroll
    for (int mi = 0; mi < 2; mi++)
        #pragma unroll
        for (int ni = 0; ni < 8; ni++)
            #pragma unroll
            for (int q = 0; q < 4; q++) acc[mi][ni][q] = 0.f;

    int l3 = lid & 7, grp = lid >> 3;
    uint32_t a_row = mrow0 + l3 + (grp & 1) * 8;
    uint32_t a_koff = (grp >> 1) * 16;
    uint32_t aH0 = sb + SA_H + a_row * SROW + a_koff;
    uint32_t aH1 = aH0 + 16 * SROW;
    uint32_t b_row = ncol0 + l3 + (grp >> 1) * 8;
    uint32_t b_koff = (grp & 1) * 16;
    uint32_t bH = sb + SB_H + b_row * SROW + b_koff;

    #pragma unroll
    for (int ks = 0; ks < 8; ks++) {
        uint32_t kb = ks * 32;
        uint32_t ah[2][4];
        ldsm4(ah[0], aH0 + kb);
        ldsm4(ah[1], aH1 + kb);
        #pragma unroll
        for (int p = 0; p < 4; p++) {        // ni pair (2p, 2p+1)
            uint32_t bh4[4];
            ldsm4(bh4, bH + p * 16 * SROW + kb);
            #pragma unroll
            for (int h = 0; h < 2; h++) {
                int ni = 2 * p + h;
                mma16816(acc[0][ni], ah[0], &bh4[2 * h]);
                mma16816(acc[1][ni], ah[1], &bh4[2 * h]);
            }
        }
    }

    // ---- epilogue: store fp16 -------------------------------------------------
    #pragma unroll
    for (int mi = 0; mi < 2; mi++) {
        int r0 = node0 + mrow0 + mi * 16 + gid;
        #pragma unroll
        for (int ni = 0; ni < 8; ni++) {
            int col = ncol0 + ni * 8 + tid4 * 2;
            if (r0 < n_nodes) {
                __half2 v; v.x = __float2half(acc[mi][ni][0]);
                           v.y = __float2half(acc[mi][ni][1]);
                *(__half2*)(g_y1h + (size_t)r0 * NCOLS + col) = v;
            }
            if (r0 + 8 < n_nodes) {
                __half2 v; v.x = __float2half(acc[mi][ni][2]);
                           v.y = __float2half(acc[mi][ni][3]);
                *(__half2*)(g_y1h + (size_t)(r0 + 8) * NCOLS + col) = v;
            }
        }
    }
}

// ------- K5: layer-1 edge scatter (8 lanes/edge, both deg scales) -------------
// R16 lesson: 8 lanes/edge keeps each warp RED.128 on 4 full h1 rows (4 lines)
// -- atomic coalescing beats index-load dedup for this kernel.
__global__ void k_scatter1(const int* __restrict__ src, const int* __restrict__ dst,
                           int n_nodes, int n_edges) {
    if (blockIdx.x == 0 && threadIdx.x < NGMAX) g_cnt[threadIdx.x] = 0;
    int i = blockIdx.x * blockDim.x + threadIdx.x;
    int tot = NREL * n_edges * 8;
    if (i >= tot) return;
    int e = i >> 3, q = i & 7;
    int r = divE(e, n_edges);
    int s = src[e], d = dst[e];
    float sc = g_rso[r * n_nodes + s] * g_rsi[r * n_nodes + d];
    uint2 raw = *(const uint2*)(g_y1h + (size_t)s * NCOLS + r * HID + q * 4);
    __half2 h01 = *(__half2*)&raw.x;
    __half2 h23 = *(__half2*)&raw.y;
    float2 f01 = __half22float2(h01);
    float2 f23 = __half22float2(h23);
    float4 v = make_float4(f01.x * sc, f01.y * sc, f23.x * sc, f23.y * sc);
    atomicAdd((float4*)(g_h1 + (size_t)d * HID + q * 4), v);
}

// ---- K6: per-node dot precompute: dot[n][r][:] = relu(h1[n]+bias) . V_r ------
__global__ __launch_bounds__(256) void k_dot(const float* __restrict__ b1,
                                             int n_nodes) {
    __shared__ float hs[32][33];
    __shared__ float Vs[NREL * HID * 2];
    __shared__ float bias[HID];
    int t = threadIdx.x;
    for (int i = t; i < NREL * HID * 2; i += 256) Vs[i] = g_V[i];
    if (t < HID) {
        float s = 0.f;
        #pragma unroll
        for (int r = 0; r < NREL; r++) s += b1[r * HID + t];
        bias[t] = s;
    }
    __syncthreads();
    int node0 = blockIdx.x * 32;
    {
        int n = t >> 3, q = t & 7;
        int gn = node0 + n;
        float4 v = make_float4(0.f, 0.f, 0.f, 0.f);
        if (gn < n_nodes) v = ((const float4*)(g_h1 + (size_t)gn * HID))[q];
        hs[n][q * 4 + 0] = fmaxf(v.x + bias[q * 4 + 0], 0.f);
        hs[n][q * 4 + 1] = fmaxf(v.y + bias[q * 4 + 1], 0.f);
        hs[n][q * 4 + 2] = fmaxf(v.z + bias[q * 4 + 2], 0.f);
        hs[n][q * 4 + 3] = fmaxf(v.w + bias[q * 4 + 3], 0.f);
    }
    __syncthreads();
    int n2 = t & 31, r2 = t >> 5;
    const float* vp = Vs + r2 * (HID * 2);
    float a0 = 0.f, a1 = 0.f;
    #pragma unroll
    for (int j = 0; j < HID; j++) {
        float h = hs[n2][j];
        a0 += h * vp[2 * j + 0];
        a1 += h * vp[2 * j + 1];
    }
    int gn2 = node0 + n2;
    if (gn2 < n_nodes)
        *(float2*)(g_dot + (size_t)gn2 * 16 + r2 * 2) = make_float2(a0, a1);
}

// ---- K7: layer-2 edge pass + mean-pool + classifier (8B gather per edge) ----
__global__ __launch_bounds__(256) void k_scatter2(const int* __restrict__ src,
                                                  const int* __restrict__ dst,
                                                  const int* __restrict__ gids,
                                                  float* __restrict__ out,
                                                  int n_nodes, int n_edges) {
    __shared__ float zs[NGMAX * 2];
    __shared__ float inv_s[NGMAX];
    int t = threadIdx.x;
    if (t < NGMAX * 2) zs[t] = 0.f;
    if (t < NGMAX) inv_s[t] = g_inv[t];
    __syncthreads();

    int te = NREL * n_edges;
    int e0 = blockIdx.x * EPB;
    #pragma unroll
    for (int it = 0; it < EPB / 256; it++) {
        int e = e0 + it * 256 + t;
        if (e < te) {
            int r = divE(e, n_edges);
            int s = src[e], d = dst[e];
            int g = gids[d];
            float coeff = g_rso[r * n_nodes + s] * g_rsi[r * n_nodes + d] * inv_s[g];
            float2 dv = *(const float2*)(g_dot + (size_t)s * 16 + r * 2);
            atomicAdd(&zs[g * 2 + 0], dv.x * coeff);
            atomicAdd(&zs[g * 2 + 1], dv.y * coeff);
        }
    }
    __syncthreads();
    if (t < NGMAX * 2) atomicAdd(&out[t], zs[t]);
}

// ---------------- launch (two capture-graph branches) --------------------------
static cudaStream_t g_s2 = nullptr;
static cudaEvent_t g_evFork = nullptr, g_evJoin = nullptr;

extern "C" void kernel_launch(void* const* d_in, const int* in_sizes, int n_in,
                              void* d_out, int out_size) {
    int off = (n_in >= 11) ? 1 : 0;
    const float* x   = (const float*)d_in[0];
    const int*   src = (const int*)d_in[1];
    const int*   dst = (const int*)d_in[2];
    const int*   gid = (const int*)d_in[3];
    const float* W1  = (const float*)d_in[4 + off];
    const float* b1  = (const float*)d_in[5 + off];
    const float* W2  = (const float*)d_in[6 + off];
    const float* b2  = (const float*)d_in[7 + off];
    const float* Wc  = (const float*)d_in[8 + off];
    const float* bc  = (const float*)d_in[9 + off];
    float* out = (float*)d_out;

    int n_nodes  = in_sizes[3];
    int n_edges  = in_sizes[1] / NREL;
    int n_graphs = out_size / 2;

    if (!g_s2) {   // one-time host-object init (first call is the uncaptured correctness run)
        cudaStreamCreateWithFlags(&g_s2, cudaStreamNonBlocking);
        cudaEventCreateWithFlags(&g_evFork, cudaEventDisableTiming);
        cudaEventCreateWithFlags(&g_evJoin, cudaEventDisableTiming);
        cudaFuncSetAttribute(k_gemm_mma, cudaFuncAttributeMaxDynamicSharedMemorySize,
                             SMEM_G);
    }

    // fork: branch B (deg + prep) runs concurrently with branch A (wconv + gemm)
    cudaEventRecord(g_evFork, 0);
    cudaStreamWaitEvent(g_s2, g_evFork, 0);

    int tot1 = NREL * n_edges + n_nodes;
    k_deg<<<(tot1 + 255) / 256, 256, 0, g_s2>>>(src, dst, gid, n_nodes, n_edges);
    int tot2 = NREL * n_nodes + NREL * HID * 2 + 2 * n_graphs + (n_nodes * HID) / 4;
    k_prep<<<(tot2 + 255) / 256, 256, 0, g_s2>>>(W2, Wc, b2, bc, out, n_nodes, n_graphs);
    cudaEventRecord(g_evJoin, g_s2);

    k_wconv<<<64, 256>>>(W1);
    k_gemm_mma<<<(n_nodes + 63) / 64, 256, SMEM_G>>>(x, n_nodes);

    // join
    cudaStreamWaitEvent(0, g_evJoin, 0);

    int tot5 = NREL * n_edges * 8;
    k_scatter1<<<(tot5 + 255) / 256, 256>>>(src, dst, n_nodes, n_edges);

    k_dot<<<(n_nodes + 31) / 32, 256>>>(b1, n_nodes);

    k_scatter2<<<(NREL * n_edges + EPB - 1) / EPB, 256>>>(src, dst, gid, out,
                                                          n_nodes, n_edges);
}